// round 2
// baseline (speedup 1.0000x reference)
#include <cuda_runtime.h>
#include <cstdint>

#define N_NODES 100000
#define N_EDGES 3200000
#define N_FEAT  512
#define N_HID   256

// ---------------- static scratch (no allocation allowed) ----------------
__device__ float d_h[(size_t)N_NODES * N_HID];     // FC output
__device__ float d_g[(size_t)N_NODES * N_HID];     // post-SpMM/PReLU
__device__ int   d_rowptr[N_NODES + 1];
__device__ int   d_cursor[N_NODES];
__device__ int   d_colidx[N_EDGES];
__device__ float d_eval[N_EDGES];
__device__ int   d_bsum[128];
__device__ float d_colsum[N_HID];
__device__ float d_v[N_HID];
__device__ int   d_is32;                           // edge_index stored as int32?

// ---------------- helpers ----------------
__device__ __forceinline__ float2 ffma2(float a, float2 b, float2 c) {
    // packed f32x2 FMA (sm_10x): 2 FMAs per issue slot
    float2 r;
    asm("{\n\t"
        ".reg .b64 ra, rb, rc;\n\t"
        "mov.b64 ra, {%4, %4};\n\t"
        "mov.b64 rb, {%5, %6};\n\t"
        "mov.b64 rc, {%2, %3};\n\t"
        "fma.rn.f32x2 rc, ra, rb, rc;\n\t"
        "mov.b64 {%0, %1}, rc;\n\t"
        "}"
        : "=f"(r.x), "=f"(r.y)
        : "f"(c.x), "f"(c.y), "f"(a), "f"(b.x), "f"(b.y));
    return r;
}

__device__ __forceinline__ int warp_incl_scan(int v) {
    int lane = threadIdx.x & 31;
#pragma unroll
    for (int o = 1; o < 32; o <<= 1) {
        int t = __shfl_up_sync(0xffffffffu, v, o);
        if (lane >= o) v += t;
    }
    return v;
}

// inclusive block scan (up to 1024 threads)
__device__ __forceinline__ int block_incl_scan(int v, int* smem) {
    int lane = threadIdx.x & 31;
    int wid  = threadIdx.x >> 5;
    int nw   = blockDim.x >> 5;
    int s = warp_incl_scan(v);
    if (lane == 31) smem[wid] = s;
    __syncthreads();
    if (wid == 0) {
        int t = (lane < nw) ? smem[lane] : 0;
        t = warp_incl_scan(t);
        if (lane < nw) smem[lane] = t;
    }
    __syncthreads();
    int add = (wid > 0) ? smem[wid - 1] : 0;
    return s + add;
}

// read edge endpoint (row: which=0 uses e, col: which=1 uses N_EDGES+e)
__device__ __forceinline__ int edge_at(const void* eidx, size_t idx) {
    if (d_is32) return ((const int*)eidx)[idx];
    return (int)((const long long*)eidx)[idx];
}

// ---------------- dtype detection (device-side, graph-capturable) ----------------
__global__ void detect_kernel(const void* eidx) {
    if (threadIdx.x == 0 && blockIdx.x == 0) {
        const long long* p = (const long long*)eidx;
        int is32 = 0;
        for (int i = 0; i < 64; i++) {
            long long v = p[i];
            if (v < 0 || v >= (long long)N_NODES) { is32 = 1; break; }
        }
        d_is32 = is32;
    }
}

// ---------------- graph build ----------------
__global__ void zero_kernel() {
    int i = blockIdx.x * blockDim.x + threadIdx.x;
    if (i < N_NODES) d_cursor[i] = 0;
    if (i < N_HID)   d_colsum[i] = 0.f;
}

__global__ void hist_kernel(const void* __restrict__ eidx) {
    int e = blockIdx.x * blockDim.x + threadIdx.x;
    if (e < N_EDGES) {
        int r = edge_at(eidx, (size_t)e);
        if ((unsigned)r < (unsigned)N_NODES)
            atomicAdd(&d_cursor[r], 1);
    }
}

__global__ void scan1_kernel() {
    __shared__ int smem[32];
    int i = blockIdx.x * 1024 + threadIdx.x;
    int c = (i < N_NODES) ? d_cursor[i] : 0;
    int s = block_incl_scan(c, smem);
    if (threadIdx.x == 1023) d_bsum[blockIdx.x] = s;
}

__global__ void scan2_kernel(int nblocks) {
    __shared__ int smem[32];
    int t = threadIdx.x;
    int v = (t < nblocks) ? d_bsum[t] : 0;
    int s = block_incl_scan(v, smem);
    if (t < nblocks) d_bsum[t] = s - v;  // exclusive
}

__global__ void scan3_kernel() {
    __shared__ int smem[32];
    int i = blockIdx.x * 1024 + threadIdx.x;
    int c = (i < N_NODES) ? d_cursor[i] : 0;
    int s = block_incl_scan(c, smem);
    int base = d_bsum[blockIdx.x];
    if (i < N_NODES) {
        int end = base + s;
        d_rowptr[i + 1] = end;
        d_cursor[i] = end - c;   // segment start; used as scatter cursor
    }
    if (i == 0) d_rowptr[0] = 0;
}

__global__ void scatter_kernel(const void* __restrict__ eidx,
                               const float* __restrict__ evals) {
    int e = blockIdx.x * blockDim.x + threadIdx.x;
    if (e < N_EDGES) {
        int r = edge_at(eidx, (size_t)e);
        int c = edge_at(eidx, (size_t)N_EDGES + e);
        if ((unsigned)r >= (unsigned)N_NODES) return;
        if ((unsigned)c >= (unsigned)N_NODES) c = 0;
        int p = atomicAdd(&d_cursor[r], 1);
        if ((unsigned)p < (unsigned)N_EDGES) {
            d_colidx[p] = c;
            d_eval[p]   = evals[e];
        }
    }
}

// ---------------- GEMM: H[m,n] = sum_k X[m,k] * W[n,k] + b[n] ----------------
// BM=128, BN=128, BK=16; 256 threads; 8x8 outputs/thread via f32x2
__global__ __launch_bounds__(256, 2)
void gemm_kernel(const float* __restrict__ A, const float* __restrict__ W,
                 const float* __restrict__ bias) {
    __shared__ float sA[16][132];
    __shared__ float sB[16][132];
    const int tid = threadIdx.x;
    const int m0 = blockIdx.y * 128;
    const int n0 = blockIdx.x * 128;
    const int tn = tid & 15;
    const int tm = tid >> 4;

    float2 acc[8][4];
#pragma unroll
    for (int i = 0; i < 8; i++)
#pragma unroll
        for (int j = 0; j < 4; j++) acc[i][j] = make_float2(0.f, 0.f);

    const int r0  = tid >> 2;          // 0..63
    const int kq0 = (tid & 3) * 4;     // 0,4,8,12
    int rowA0 = m0 + r0;      if (rowA0 > N_NODES - 1) rowA0 = N_NODES - 1;
    int rowA1 = m0 + r0 + 64; if (rowA1 > N_NODES - 1) rowA1 = N_NODES - 1;
    const float* a0p = A + (size_t)rowA0 * N_FEAT + kq0;
    const float* a1p = A + (size_t)rowA1 * N_FEAT + kq0;
    const float* b0p = W + (size_t)(n0 + r0) * N_FEAT + kq0;
    const float* b1p = W + (size_t)(n0 + r0 + 64) * N_FEAT + kq0;

    for (int k0 = 0; k0 < N_FEAT; k0 += 16) {
        float4 va0 = *(const float4*)(a0p + k0);
        float4 va1 = *(const float4*)(a1p + k0);
        float4 vb0 = *(const float4*)(b0p + k0);
        float4 vb1 = *(const float4*)(b1p + k0);
        __syncthreads();
        sA[kq0 + 0][r0] = va0.x; sA[kq0 + 1][r0] = va0.y;
        sA[kq0 + 2][r0] = va0.z; sA[kq0 + 3][r0] = va0.w;
        sA[kq0 + 0][r0 + 64] = va1.x; sA[kq0 + 1][r0 + 64] = va1.y;
        sA[kq0 + 2][r0 + 64] = va1.z; sA[kq0 + 3][r0 + 64] = va1.w;
        sB[kq0 + 0][r0] = vb0.x; sB[kq0 + 1][r0] = vb0.y;
        sB[kq0 + 2][r0] = vb0.z; sB[kq0 + 3][r0] = vb0.w;
        sB[kq0 + 0][r0 + 64] = vb1.x; sB[kq0 + 1][r0 + 64] = vb1.y;
        sB[kq0 + 2][r0 + 64] = vb1.z; sB[kq0 + 3][r0 + 64] = vb1.w;
        __syncthreads();
#pragma unroll
        for (int kk = 0; kk < 16; kk++) {
            float4 a0v = *(const float4*)&sA[kk][tm * 8];
            float4 a1v = *(const float4*)&sA[kk][tm * 8 + 4];
            float4 b0v = *(const float4*)&sB[kk][tn * 8];
            float4 b1v = *(const float4*)&sB[kk][tn * 8 + 4];
            float av[8] = {a0v.x, a0v.y, a0v.z, a0v.w, a1v.x, a1v.y, a1v.z, a1v.w};
            float2 bp[4] = {make_float2(b0v.x, b0v.y), make_float2(b0v.z, b0v.w),
                            make_float2(b1v.x, b1v.y), make_float2(b1v.z, b1v.w)};
#pragma unroll
            for (int i = 0; i < 8; i++)
#pragma unroll
                for (int j = 0; j < 4; j++)
                    acc[i][j] = ffma2(av[i], bp[j], acc[i][j]);
        }
    }

    const float4 bs0 = *(const float4*)&bias[n0 + tn * 8];
    const float4 bs1 = *(const float4*)&bias[n0 + tn * 8 + 4];
#pragma unroll
    for (int i = 0; i < 8; i++) {
        int gm = m0 + tm * 8 + i;
        if (gm < N_NODES) {
            float4 o0 = make_float4(acc[i][0].x + bs0.x, acc[i][0].y + bs0.y,
                                    acc[i][1].x + bs0.z, acc[i][1].y + bs0.w);
            float4 o1 = make_float4(acc[i][2].x + bs1.x, acc[i][2].y + bs1.y,
                                    acc[i][3].x + bs1.z, acc[i][3].y + bs1.w);
            *(float4*)&d_h[(size_t)gm * N_HID + n0 + tn * 8]     = o0;
            *(float4*)&d_h[(size_t)gm * N_HID + n0 + tn * 8 + 4] = o1;
        }
    }
}

// ---------------- SpMM + PReLU: g[n,:] = prelu(sum_e w_e * h[col_e,:]) ----------------
__global__ __launch_bounds__(256)
void spmm_kernel(const float* __restrict__ prelu_a) {
    const int node = blockIdx.x;
    const int j = threadIdx.x;
    const int beg = d_rowptr[node];
    const int end = d_rowptr[node + 1];
    float acc = 0.f;
    int e = beg;
    for (; e + 4 <= end; e += 4) {
        int c0 = d_colidx[e], c1 = d_colidx[e + 1];
        int c2 = d_colidx[e + 2], c3 = d_colidx[e + 3];
        float w0 = d_eval[e], w1 = d_eval[e + 1];
        float w2 = d_eval[e + 2], w3 = d_eval[e + 3];
        float v0 = d_h[(size_t)c0 * N_HID + j];
        float v1 = d_h[(size_t)c1 * N_HID + j];
        float v2 = d_h[(size_t)c2 * N_HID + j];
        float v3 = d_h[(size_t)c3 * N_HID + j];
        acc += w0 * v0; acc += w1 * v1; acc += w2 * v2; acc += w3 * v3;
    }
    for (; e < end; ++e)
        acc += d_eval[e] * d_h[(size_t)d_colidx[e] * N_HID + j];
    float a0 = prelu_a[0];
    acc = (acc >= 0.f) ? acc : a0 * acc;
    d_g[(size_t)node * N_HID + j] = acc;
}

// ---------------- column sum of g (for mean over nodes) ----------------
__global__ void colsum_kernel() {
    const int j = threadIdx.x;
    const int start = blockIdx.x * 512;
    int stop = start + 512;
    if (stop > N_NODES) stop = N_NODES;
    float s = 0.f;
    for (int n = start; n < stop; n++) s += d_g[(size_t)n * N_HID + j];
    atomicAdd(&d_colsum[j], s);
}

// ---------------- v = bil_w @ sigmoid(mean) ----------------
__global__ void vker(const float* __restrict__ bw) {
    __shared__ float ssig[N_HID];
    int t = threadIdx.x;
    ssig[t] = 1.f / (1.f + expf(-d_colsum[t] * (1.f / (float)N_NODES)));
    __syncthreads();
    float acc = 0.f;
#pragma unroll 8
    for (int g = 0; g < N_HID; g++) acc += bw[t * N_HID + g] * ssig[g];
    d_v[t] = acc;
}

// ---------------- score[n] = dot(g[n], v) + bil_b ----------------
__global__ __launch_bounds__(256)
void score_kernel(const float* __restrict__ bb, float* __restrict__ out) {
    const int warp = threadIdx.x >> 5;
    const int lane = threadIdx.x & 31;
    const int node = blockIdx.x * 8 + warp;
    if (node >= N_NODES) return;
    const float4* gr = (const float4*)&d_g[(size_t)node * N_HID];
    const float4* vv = (const float4*)d_v;
    float acc = 0.f;
#pragma unroll
    for (int i = lane; i < 64; i += 32) {
        float4 a = gr[i];
        float4 b = vv[i];
        acc += a.x * b.x + a.y * b.y + a.z * b.z + a.w * b.w;
    }
#pragma unroll
    for (int o = 16; o > 0; o >>= 1) acc += __shfl_xor_sync(0xffffffffu, acc, o);
    if (lane == 0) out[node] = acc + bb[0];
}

// ---------------- launch ----------------
extern "C" void kernel_launch(void* const* d_in, const int* in_sizes, int n_in,
                              void* d_out, int out_size) {
    const float* x1  = (const float*)d_in[0];
    const float* x2  = (const float*)d_in[1];
    const float* ev  = (const float*)d_in[2];
    const float* fcw = (const float*)d_in[3];
    const float* fcb = (const float*)d_in[4];
    const float* pa  = (const float*)d_in[5];
    const float* bw  = (const float*)d_in[6];
    const float* bb  = (const float*)d_in[7];
    const void*  ei  = (const void*)d_in[8];
    float* out = (float*)d_out;

    const int scan_blocks = (N_NODES + 1023) / 1024;   // 98
    const int edge_blocks = (N_EDGES + 255) / 256;     // 12500

    // CSR build (per call; part of timed work)
    detect_kernel<<<1, 32>>>(ei);
    zero_kernel<<<(N_NODES + 255) / 256, 256>>>();
    hist_kernel<<<edge_blocks, 256>>>(ei);
    scan1_kernel<<<scan_blocks, 1024>>>();
    scan2_kernel<<<1, 128>>>(scan_blocks);
    scan3_kernel<<<scan_blocks, 1024>>>();
    scatter_kernel<<<edge_blocks, 256>>>(ei, ev);

    dim3 ggrid(2, (N_NODES + 127) / 128);

    // graph 1
    gemm_kernel<<<ggrid, 256>>>(x1, fcw, fcb);
    spmm_kernel<<<N_NODES, 256>>>(pa);
    colsum_kernel<<<(N_NODES + 511) / 512, 256>>>();
    vker<<<1, N_HID>>>(bw);
    score_kernel<<<(N_NODES + 7) / 8, 256>>>(bb, out);

    // graph 2 (reuses d_h/d_g; v already fixed)
    gemm_kernel<<<ggrid, 256>>>(x2, fcw, fcb);
    spmm_kernel<<<N_NODES, 256>>>(pa);
    score_kernel<<<(N_NODES + 7) / 8, 256>>>(bb, out + N_NODES);
}